// round 10
// baseline (speedup 1.0000x reference)
#include <cuda_runtime.h>

// Problem constants (fixed by setup_inputs)
#define CC      4
#define HH      256
#define WW      256
#define EE      32
#define OO      32
#define NN      125                  // (256-7)/2+1
#define NQ      (NN * NN)            // 15625
#define NQS     15632                // zT q-stride (pad cols 15625..15631 garbage-ok)
#define DD      196                  // C*7*7 ; d = (c*7+r)*7 + s
#define NSV     8                    // survivor slots per query
#define DIST_SCALE 10.0f
#define W_THR   1e-7f
#define FULL    0xFFFFFFFFu

__device__ float g_ZT[DD * NQS];     // transposed aggregation zT[d][q] (~12.3MB)
__device__ uint2 g_SV[NQ * NSV];     // survivor list: (po, bits(w)) (1MB)

// ---------------------------------------------------------------------------
// K_dist: one query per warp. p1 coalesced distances + p2 softmax; writes the
// <=8 surviving (po, w) pairs in deterministic lane-rank order (w=0 padding).
// Denominator is exact over all 32 candidates.
// ---------------------------------------------------------------------------
__global__ __launch_bounds__(256) void dist_kernel(const float* __restrict__ xe,
                                                   const float* __restrict__ ye,
                                                   const int*   __restrict__ inds) {
    const int lane = threadIdx.x & 31;
    const int wrp  = threadIdx.x >> 5;
    const int q    = blockIdx.x * 8 + wrp;
    if (q >= NQ) return;                           // warp-uniform; no block syncs

    __shared__ float s_d2[8][OO];

    // ---- p1: coalesced distances (8 lanes per candidate row) ----
    const int g  = lane >> 3;
    const int ch = lane & 7;
    const float4 y4 = reinterpret_cast<const float4*>(ye + q * EE)[ch];
    const int p_l   = inds[q * OO + lane];

    float acck[8];
#pragma unroll
    for (int k = 0; k < 8; k++) {
        const int po = __shfl_sync(FULL, p_l, k * 4 + g);
        const float4 v = reinterpret_cast<const float4*>(xe + po * EE)[ch];
        const float dx = v.x - y4.x, dy = v.y - y4.y;
        const float dz = v.z - y4.z, dw = v.w - y4.w;
        acck[k] = dx * dx + dy * dy + dz * dz + dw * dw;
    }
#pragma unroll
    for (int k = 0; k < 8; k++) {
        acck[k] += __shfl_xor_sync(FULL, acck[k], 1);
        acck[k] += __shfl_xor_sync(FULL, acck[k], 2);
        acck[k] += __shfl_xor_sync(FULL, acck[k], 4);
    }
    if (ch == 0) {
#pragma unroll
        for (int k = 0; k < 8; k++) s_d2[wrp][k * 4 + g] = acck[k];
    }
    __syncwarp();
    const float d2 = s_d2[wrp][lane];

    // ---- p2: softmax + threshold ----
    float m = d2;
#pragma unroll
    for (int off = 16; off; off >>= 1)
        m = fminf(m, __shfl_xor_sync(FULL, m, off));
    const float ev = __expf(-DIST_SCALE * (d2 - m));
    float sum = ev;
#pragma unroll
    for (int off = 16; off; off >>= 1)
        sum += __shfl_xor_sync(FULL, sum, off);
    const float w = ev / sum;

    const unsigned surv = __ballot_sync(FULL, w >= W_THR);

    // ---- slot write: lane s (<8) emits the s-th survivor (or w=0 pad) ----
    int lo = __fns(surv, 0, lane + 1);             // ~0u if none
    const bool valid = (lane < NSV) && (lo != -1);
    const int  ls  = valid ? lo : 0;
    const float wv = __shfl_sync(FULL, w,   ls);
    const int   pv = __shfl_sync(FULL, p_l, ls);
    if (lane < NSV) {
        uint2 slot;
        slot.x = valid ? (unsigned)pv : 0u;
        slot.y = valid ? __float_as_uint(wv) : 0u;
        g_SV[q * NSV + lane] = slot;
    }
}

// ---------------------------------------------------------------------------
// K_gath: one query per warp. Reads the 8-slot list (one coalesced LDG.64 row),
// row-grouped gather from x, transposed zT store.
// ---------------------------------------------------------------------------
__global__ __launch_bounds__(256) void gath_kernel(const float* __restrict__ x) {
    const int lane = threadIdx.x & 31;
    const int wrp  = threadIdx.x >> 5;
    const int q0   = blockIdx.x * 8;
    const int q    = q0 + wrp;

    __shared__ float s_z[8][DD];

    if (q < NQ) {                                  // warp-uniform
        uint2 slot = make_uint2(0u, 0u);
        if (lane < NSV) slot = g_SV[q * NSV + lane];
        const float w_l = __uint_as_float(slot.y);
        const int   p_l = (int)slot.x;

        // ---- row-grouped gather setup ----
        const int row3 = lane >> 2;
        const int pair = lane & 3;
        int  offs[4];
        bool act [4];
        int  drow[4];
#pragma unroll
        for (int t = 0; t < 4; t++) {
            const int row = t * 8 + row3;
            act[t]  = (row < 28);
            const int rc = act[t] ? row : 0;
            const int c  = rc / 7;
            const int r  = rc - c * 7;
            offs[t] = c * (HH * WW) + r * WW + pair * 2;
            drow[t] = rc * 7;
        }

        float2 acc[4];
#pragma unroll
        for (int t = 0; t < 4; t++) acc[t] = make_float2(0.f, 0.f);

#pragma unroll 2
        for (int s = 0; s < NSV; s++) {
            const float ws = __shfl_sync(FULL, w_l, s);
            if (ws == 0.f) break;                  // warp-uniform
            const int po = __shfl_sync(FULL, p_l, s);
            const int pi = po / NN;
            const int pj = po - pi * NN;
            const int pb = pi * (2 * WW) + pj * 2;
#pragma unroll
            for (int t = 0; t < 4; t++) {
                if (act[t]) {
                    const float2 v = *reinterpret_cast<const float2*>(
                        x + offs[t] + pb);
                    acc[t].x += ws * v.x;
                    acc[t].y += ws * v.y;
                }
            }
        }

#pragma unroll
        for (int t = 0; t < 4; t++) {
            if (act[t]) {
                const int d0 = drow[t] + pair * 2;
                s_z[wrp][d0] = acc[t].x;
                if (pair < 3) s_z[wrp][d0 + 1] = acc[t].y;
            }
        }
    }

    __syncthreads();

    // ---- transposed store, unguarded (zT q-pad absorbs last-CTA garbage) ----
    const int tid = threadIdx.x;
#pragma unroll
    for (int k = 0; k < 6; k++) {
        const int mIdx = tid + 256 * k;
        const int d  = mIdx >> 3;
        const int qq = mIdx & 7;
        g_ZT[d * NQS + q0 + qq] = s_z[qq][d];
    }
    if (tid < 32) {
        const int mIdx = tid + 1536;
        const int d  = mIdx >> 3;
        const int qq = mIdx & 7;
        g_ZT[d * NQS + q0 + qq] = s_z[qq][d];
    }
}

// ---------------------------------------------------------------------------
// K_fold: unchanged from round 9 (measured 8.1us cold / ~4us warm).
// ---------------------------------------------------------------------------
__constant__ int c_ridx[28] = {0,0,0,0,0,0,0, 1,1,1,1,1,1,1, 2,2,2,2,2,2,2, 3,3,3,3,3,3,3};
__constant__ int c_s   [28] = {0,1,2,3,4,5,6, 0,1,2,3,4,5,6, 0,1,2,3,4,5,6, 0,1,2,3,4,5,6};

#define FW 132                        // [0..3]=0 pad, data 4..128, [129..131]=0 pad
__global__ __launch_bounds__(256) void fold_kernel(float* __restrict__ out) {
    const int c   = blockIdx.x >> 8;
    const int h   = blockIdx.x & 255;
    const int par = h & 1;

    __shared__ float s_rows[28][FW];

    const int lane = threadIdx.x & 31;
    const int wrp  = threadIdx.x >> 5;

#pragma unroll
    for (int k = 0; k < 4; k++) {
        const int rr = wrp + 8 * k;
        if (rr >= 28) break;                      // warp-uniform
        const int ridx = c_ridx[rr];
        const int s    = c_s[rr];
        const int r    = par + 2 * ridx;
        const int i2   = h - r;
        float* dst = &s_rows[rr][0];
        if ((r <= 6) && (i2 >= 0) && (i2 <= 2 * (NN - 1))) {
            const float* src = g_ZT + ((c * 7 + r) * 7 + s) * NQS + (i2 >> 1) * NN;
            dst[4 + lane]       = src[lane];
            dst[4 + lane + 32]  = src[lane + 32];
            dst[4 + lane + 64]  = src[lane + 64];
            dst[4 + lane + 96]  = src[lane + 96];
        } else {
            dst[4 + lane]       = 0.f;
            dst[4 + lane + 32]  = 0.f;
            dst[4 + lane + 64]  = 0.f;
            dst[4 + lane + 96]  = 0.f;
        }
        __syncwarp();
        if (lane < 4) dst[lane] = 0.f;
        if (lane < 3) dst[129 + lane] = 0.f;      // also kills staging overshoot
    }
    __syncthreads();

    if (threadIdx.x < 128) {
        const int t = threadIdx.x;
        float acc0 = 0.f, acc1 = 0.f;
#pragma unroll
        for (int ridx = 0; ridx < 4; ridx++) {
            const int rb = ridx * 7;
#pragma unroll
            for (int si = 0; si < 4; si++)
                acc0 += s_rows[rb + 2 * si][4 + t - si];
#pragma unroll
            for (int si = 0; si < 3; si++)
                acc1 += s_rows[rb + 1 + 2 * si][4 + t - si];
        }
        reinterpret_cast<float2*>(out + blockIdx.x * 256)[t] =
            make_float2(acc0, acc1);
    }
}

// Diagnostic no-op: shifts ncu's "-s 5 -c 1" capture onto gath_kernel
// (launch #6 = 2nd kernel when 4 kernels per call). Remove once profiled.
__global__ void noop_kernel() {}

// ---------------------------------------------------------------------------
extern "C" void kernel_launch(void* const* d_in, const int* in_sizes, int n_in,
                              void* d_out, int out_size) {
    const float* x    = (const float*)d_in[0];
    const float* xe   = (const float*)d_in[1];
    const float* ye   = (const float*)d_in[2];
    const int*   inds = (const int*)  d_in[3];
    float*       out  = (float*)d_out;
    (void)in_sizes; (void)n_in; (void)out_size;

    dist_kernel<<<(NQ + 7) / 8, 256>>>(xe, ye, inds);
    gath_kernel<<<(NQ + 7) / 8, 256>>>(x);
    fold_kernel<<<CC * HH, 256>>>(out);
    noop_kernel<<<1, 32>>>();
}

// round 11
// speedup vs baseline: 1.1934x; 1.1934x over previous
#include <cuda_runtime.h>

// Problem constants (fixed by setup_inputs)
#define CC      4
#define HH      256
#define WW      256
#define EE      32
#define OO      32
#define NN      125                  // (256-7)/2+1
#define NQ      (NN * NN)            // 15625
#define DIST_SCALE 10.0f
#define W_THR   1e-7f
#define FULL    0xFFFFFFFFu

// ---------------------------------------------------------------------------
// Fused kernel: one query per warp, 8 warps/CTA, NO block-level coupling.
//  p1: coalesced distances (8 lanes/candidate row, 4 candidates per LDG.128)
//  p2: warp softmax + ballot threshold (exact denominator, deterministic order)
//  p3: row-grouped survivor gather from x (4x LDG.64 per survivor)
//  p4: scatter-add the accumulated patch into out at q's own footprint
//      (<=7 REDG.32 per lane; overlaps with neighbor queries resolved by L2
//       atomic ALU; out pre-zeroed by memset).
// ---------------------------------------------------------------------------
__global__ __launch_bounds__(256) void agg_scatter_kernel(
        const float* __restrict__ x,
        const float* __restrict__ xe,
        const float* __restrict__ ye,
        const int*   __restrict__ inds,
        float*       __restrict__ out) {
    const int lane = threadIdx.x & 31;
    const int wrp  = threadIdx.x >> 5;
    const int q    = blockIdx.x * 8 + wrp;
    if (q >= NQ) return;                           // warp-uniform

    __shared__ float s_d2[8][OO];

    // ---- p1: coalesced distances ----
    const int g  = lane >> 3;                      // candidate group in instr
    const int ch = lane & 7;                       // float4 chunk of row
    const float4 y4 = reinterpret_cast<const float4*>(ye + q * EE)[ch];
    const int p_l   = inds[q * OO + lane];

    float acck[8];
#pragma unroll
    for (int k = 0; k < 8; k++) {
        const int po = __shfl_sync(FULL, p_l, k * 4 + g);
        const float4 v = reinterpret_cast<const float4*>(xe + po * EE)[ch];
        const float dx = v.x - y4.x, dy = v.y - y4.y;
        const float dz = v.z - y4.z, dw = v.w - y4.w;
        acck[k] = dx * dx + dy * dy + dz * dz + dw * dw;
    }
#pragma unroll
    for (int k = 0; k < 8; k++) {
        acck[k] += __shfl_xor_sync(FULL, acck[k], 1);
        acck[k] += __shfl_xor_sync(FULL, acck[k], 2);
        acck[k] += __shfl_xor_sync(FULL, acck[k], 4);
    }
    if (ch == 0) {
#pragma unroll
        for (int k = 0; k < 8; k++) s_d2[wrp][k * 4 + g] = acck[k];
    }
    __syncwarp();
    const float d2 = s_d2[wrp][lane];

    // ---- p2: softmax + threshold ----
    float m = d2;
#pragma unroll
    for (int off = 16; off; off >>= 1)
        m = fminf(m, __shfl_xor_sync(FULL, m, off));
    const float ev = __expf(-DIST_SCALE * (d2 - m));
    float sum = ev;
#pragma unroll
    for (int off = 16; off; off >>= 1)
        sum += __shfl_xor_sync(FULL, sum, off);
    const float w = ev / sum;

    const unsigned surv = __ballot_sync(FULL, w >= W_THR);
    const int ks = __popc(surv);

    // ---- p3: row-grouped survivor gather from x ----
    // lane (row3,pair): rows t*8+row3 (t=0..3), floats s=2*pair, 2*pair+1
    const int row3 = lane >> 2;
    const int pair = lane & 3;
    int  offs[4];
    bool act [4];
#pragma unroll
    for (int t = 0; t < 4; t++) {
        const int row = t * 8 + row3;
        act[t]  = (row < 28);
        const int rc = act[t] ? row : 0;
        const int c  = rc / 7;
        const int r  = rc - c * 7;
        offs[t] = c * (HH * WW) + r * WW + pair * 2;
    }

    float2 acc[4];
#pragma unroll
    for (int t = 0; t < 4; t++) acc[t] = make_float2(0.f, 0.f);

    for (int s = 0; s < ks; s++) {
        const int   lo = __fns(surv, 0, s + 1);
        const float ws = __shfl_sync(FULL, w,   lo);
        const int   po = __shfl_sync(FULL, p_l, lo);
        const int   pi = po / NN;
        const int   pj = po - pi * NN;
        const int   pb = pi * (2 * WW) + pj * 2;
#pragma unroll
        for (int t = 0; t < 4; t++) {
            if (act[t]) {
                const float2 v = *reinterpret_cast<const float2*>(
                    x + offs[t] + pb);             // s=7 over-read is in-image pad
                acc[t].x += ws * v.x;
                acc[t].y += ws * v.y;
            }
        }
    }

    // ---- p4: scatter-add into out at q's own footprint ----
    const int qi  = q / NN;
    const int qj  = q - qi * NN;
    const int pbq = qi * (2 * WW) + qj * 2;
#pragma unroll
    for (int t = 0; t < 4; t++) {
        if (act[t]) {
            float* dst = out + offs[t] + pbq;
            atomicAdd(dst, acc[t].x);              // s = 2*pair
            if (pair < 3) atomicAdd(dst + 1, acc[t].y);  // s = 2*pair+1 (skip s=7)
        }
    }
}

// ---------------------------------------------------------------------------
extern "C" void kernel_launch(void* const* d_in, const int* in_sizes, int n_in,
                              void* d_out, int out_size) {
    const float* x    = (const float*)d_in[0];
    const float* xe   = (const float*)d_in[1];
    const float* ye   = (const float*)d_in[2];
    const int*   inds = (const int*)  d_in[3];
    float*       out  = (float*)d_out;
    (void)in_sizes; (void)n_in;

    cudaMemsetAsync(out, 0, (size_t)out_size * sizeof(float));
    agg_scatter_kernel<<<(NQ + 7) / 8, 256>>>(x, xe, ye, inds, out);
}

// round 12
// speedup vs baseline: 1.3292x; 1.1138x over previous
#include <cuda_runtime.h>

// Problem constants (fixed by setup_inputs)
#define CC      4
#define HH      256
#define WW      256
#define EE      32
#define OO      32
#define NN      125                  // (256-7)/2+1
#define NQ      (NN * NN)            // 15625
#define DIST_SCALE 10.0f
#define W_THR   1e-7f
#define FULL    0xFFFFFFFFu

// ---------------------------------------------------------------------------
// Fused kernel: one query per warp, 8 warps/CTA, no block-level coupling.
//  p1: coalesced distances (8 lanes/candidate row, 4 candidates per LDG.128)
//  p2: warp softmax + ballot threshold (exact denominator, deterministic)
//  p3: row-grouped survivor gather from x (4x LDG.64 per survivor)
//  p4: VECTOR scatter-add (red.global.add.v2.f32): one 8B reduction per lane
//      per t -> footprint lines touched once, 4 atomic instrs/warp.
// ---------------------------------------------------------------------------
__global__ __launch_bounds__(256) void agg_scatter_kernel(
        const float* __restrict__ x,
        const float* __restrict__ xe,
        const float* __restrict__ ye,
        const int*   __restrict__ inds,
        float*       __restrict__ out) {
    const int lane = threadIdx.x & 31;
    const int wrp  = threadIdx.x >> 5;
    const int q    = blockIdx.x * 8 + wrp;
    if (q >= NQ) return;                           // warp-uniform

    __shared__ float s_d2[8][OO];

    // ---- p1: coalesced distances ----
    const int g  = lane >> 3;                      // candidate group in instr
    const int ch = lane & 7;                       // float4 chunk of row
    const float4 y4 = reinterpret_cast<const float4*>(ye + q * EE)[ch];
    const int p_l   = inds[q * OO + lane];

    float acck[8];
#pragma unroll
    for (int k = 0; k < 8; k++) {
        const int po = __shfl_sync(FULL, p_l, k * 4 + g);
        const float4 v = reinterpret_cast<const float4*>(xe + po * EE)[ch];
        const float dx = v.x - y4.x, dy = v.y - y4.y;
        const float dz = v.z - y4.z, dw = v.w - y4.w;
        acck[k] = dx * dx + dy * dy + dz * dz + dw * dw;
    }
#pragma unroll
    for (int k = 0; k < 8; k++) {
        acck[k] += __shfl_xor_sync(FULL, acck[k], 1);
        acck[k] += __shfl_xor_sync(FULL, acck[k], 2);
        acck[k] += __shfl_xor_sync(FULL, acck[k], 4);
    }
    if (ch == 0) {
#pragma unroll
        for (int k = 0; k < 8; k++) s_d2[wrp][k * 4 + g] = acck[k];
    }
    __syncwarp();
    const float d2 = s_d2[wrp][lane];

    // ---- p2: softmax + threshold ----
    float m = d2;
#pragma unroll
    for (int off = 16; off; off >>= 1)
        m = fminf(m, __shfl_xor_sync(FULL, m, off));
    const float ev = __expf(-DIST_SCALE * (d2 - m));
    float sum = ev;
#pragma unroll
    for (int off = 16; off; off >>= 1)
        sum += __shfl_xor_sync(FULL, sum, off);
    const float w = ev / sum;

    const unsigned surv = __ballot_sync(FULL, w >= W_THR);
    const int ks = __popc(surv);

    // ---- p3: row-grouped survivor gather from x ----
    // lane (row3,pair): rows t*8+row3 (t=0..3), floats s=2*pair, 2*pair+1
    const int row3 = lane >> 2;
    const int pair = lane & 3;
    int  offs[4];
    bool act [4];
#pragma unroll
    for (int t = 0; t < 4; t++) {
        const int row = t * 8 + row3;
        act[t]  = (row < 28);
        const int rc = act[t] ? row : 0;
        const int c  = rc / 7;
        const int r  = rc - c * 7;
        offs[t] = c * (HH * WW) + r * WW + pair * 2;
    }

    float2 acc[4];
#pragma unroll
    for (int t = 0; t < 4; t++) acc[t] = make_float2(0.f, 0.f);

    for (int s = 0; s < ks; s++) {
        const int   lo = __fns(surv, 0, s + 1);
        const float ws = __shfl_sync(FULL, w,   lo);
        const int   po = __shfl_sync(FULL, p_l, lo);
        const int   pi = po / NN;
        const int   pj = po - pi * NN;
        const int   pb = pi * (2 * WW) + pj * 2;
#pragma unroll
        for (int t = 0; t < 4; t++) {
            if (act[t]) {
                const float2 v = *reinterpret_cast<const float2*>(
                    x + offs[t] + pb);             // s=7 over-read is in-image
                acc[t].x += ws * v.x;
                acc[t].y += ws * v.y;
            }
        }
    }

    // ---- p4: vector scatter-add into out at q's own footprint ----
    // pair==3 lane's .y accumulated s=7 garbage: zero it; red.v2 then adds
    // 0.0f to the neighboring real pixel (col 2j+7 <= 255) - value-neutral.
    const int qi  = q / NN;
    const int qj  = q - qi * NN;
    const int pbq = qi * (2 * WW) + qj * 2;
    const bool p3e = (pair == 3);
#pragma unroll
    for (int t = 0; t < 4; t++) {
        if (act[t]) {
            const float ay = p3e ? 0.f : acc[t].y;
            float* dst = out + offs[t] + pbq;      // 8B-aligned (offset even)
            asm volatile("red.global.add.v2.f32 [%0], {%1, %2};"
                         :: "l"(dst), "f"(acc[t].x), "f"(ay)
                         : "memory");
        }
    }
}

// ---------------------------------------------------------------------------
extern "C" void kernel_launch(void* const* d_in, const int* in_sizes, int n_in,
                              void* d_out, int out_size) {
    const float* x    = (const float*)d_in[0];
    const float* xe   = (const float*)d_in[1];
    const float* ye   = (const float*)d_in[2];
    const int*   inds = (const int*)  d_in[3];
    float*       out  = (float*)d_out;
    (void)in_sizes; (void)n_in;

    cudaMemsetAsync(out, 0, (size_t)out_size * sizeof(float));
    agg_scatter_kernel<<<(NQ + 7) / 8, 256>>>(x, xe, ye, inds, out);
}

// round 13
// speedup vs baseline: 1.3500x; 1.0156x over previous
#include <cuda_runtime.h>

// Problem constants (fixed by setup_inputs)
#define CC      4
#define HH      256
#define WW      256
#define EE      32
#define OO      32
#define NN      125                  // (256-7)/2+1
#define NQ      (NN * NN)            // 15625
#define DIST_SCALE 10.0f
#define W_THR   1e-7f
#define FULL    0xFFFFFFFFu

// ---------------------------------------------------------------------------
// Fused kernel: one query per warp, 8 warps/CTA, no block-level coupling,
// no shared memory.
//  p1: coalesced distances (8 lanes/candidate row, 4 candidates per LDG.128),
//      split-exchange reduction (7 shfl instead of 24, no smem round-trip);
//      lane ends holding d2 of candidate o' = (lane&7)*4 + (lane>>3).
//  p2: warp softmax + ballot threshold (order-symmetric -> permutation-safe)
//  p3: row-grouped survivor gather from x (4x LDG.64 per survivor; pb hoisted)
//  p4: vector scatter-add (red.global.add.v2.f32) into q's own footprint.
// ---------------------------------------------------------------------------
__global__ __launch_bounds__(256) void agg_scatter_kernel(
        const float* __restrict__ x,
        const float* __restrict__ xe,
        const float* __restrict__ ye,
        const int*   __restrict__ inds,
        float*       __restrict__ out) {
    const int lane = threadIdx.x & 31;
    const int wrp  = threadIdx.x >> 5;
    const int q    = blockIdx.x * 8 + wrp;
    if (q >= NQ) return;                           // warp-uniform

    // ---- p1: coalesced distances ----
    const int g  = lane >> 3;                      // candidate group in instr
    const int ch = lane & 7;                       // float4 chunk of row
    const float4 y4 = reinterpret_cast<const float4*>(ye + q * EE)[ch];
    const int p_l   = inds[q * OO + lane];         // candidate `lane`'s patch

    float a[8];
#pragma unroll
    for (int k = 0; k < 8; k++) {
        const int po = __shfl_sync(FULL, p_l, k * 4 + g);
        const float4 v = reinterpret_cast<const float4*>(xe + po * EE)[ch];
        const float dx = v.x - y4.x, dy = v.y - y4.y;
        const float dz = v.z - y4.z, dw = v.w - y4.w;
        a[k] = dx * dx + dy * dy + dz * dz + dw * dw;
    }

    // split-exchange reduction over the 8-lane ch dimension:
    // halves value count each stage; lane ends with full sum of a[ch].
#pragma unroll
    for (int i = 0; i < 4; i++) {                  // stage m=4
        const float send = (lane & 4) ? a[i] : a[i + 4];
        const float keep = (lane & 4) ? a[i + 4] : a[i];
        a[i] = keep + __shfl_xor_sync(FULL, send, 4);
    }
#pragma unroll
    for (int i = 0; i < 2; i++) {                  // stage m=2
        const float send = (lane & 2) ? a[i] : a[i + 2];
        const float keep = (lane & 2) ? a[i + 2] : a[i];
        a[i] = keep + __shfl_xor_sync(FULL, send, 2);
    }
    const float send1 = (lane & 1) ? a[0] : a[1];  // stage m=1
    const float keep1 = (lane & 1) ? a[1] : a[0];
    const float d2 = keep1 + __shfl_xor_sync(FULL, send1, 1);

    // lane now holds d2 of candidate o' = ch*4 + g; realign its patch index
    const int my_o = (lane & 7) * 4 + (lane >> 3);
    const int my_p = __shfl_sync(FULL, p_l, my_o);

    // hoisted gather base for this candidate (was per-survivor divide)
    const int pi = my_p / NN;
    const int pj = my_p - pi * NN;
    const int pb_l = pi * (2 * WW) + pj * 2;

    // ---- p2: softmax + threshold (order-symmetric over permuted lanes) ----
    float m = d2;
#pragma unroll
    for (int off = 16; off; off >>= 1)
        m = fminf(m, __shfl_xor_sync(FULL, m, off));
    const float ev = __expf(-DIST_SCALE * (d2 - m));
    float sum = ev;
#pragma unroll
    for (int off = 16; off; off >>= 1)
        sum += __shfl_xor_sync(FULL, sum, off);
    const float w = ev / sum;

    const unsigned surv = __ballot_sync(FULL, w >= W_THR);
    const int ks = __popc(surv);

    // ---- p3: row-grouped survivor gather from x ----
    // lane (row3,pair): rows t*8+row3 (t=0..3), floats s=2*pair, 2*pair+1
    const int row3 = lane >> 2;
    const int pair = lane & 3;
    int  offs[4];
    bool act [4];
#pragma unroll
    for (int t = 0; t < 4; t++) {
        const int row = t * 8 + row3;
        act[t]  = (row < 28);
        const int rc = act[t] ? row : 0;
        const int c  = rc / 7;
        const int r  = rc - c * 7;
        offs[t] = c * (HH * WW) + r * WW + pair * 2;
    }

    float2 acc[4];
#pragma unroll
    for (int t = 0; t < 4; t++) acc[t] = make_float2(0.f, 0.f);

    for (int s = 0; s < ks; s++) {
        const int   lo = __fns(surv, 0, s + 1);
        const float ws = __shfl_sync(FULL, w,    lo);
        const int   pb = __shfl_sync(FULL, pb_l, lo);
#pragma unroll
        for (int t = 0; t < 4; t++) {
            if (act[t]) {
                const float2 v = *reinterpret_cast<const float2*>(
                    x + offs[t] + pb);             // s=7 over-read is in-image
                acc[t].x += ws * v.x;
                acc[t].y += ws * v.y;
            }
        }
    }

    // ---- p4: vector scatter-add into out at q's own footprint ----
    const int qi  = q / NN;
    const int qj  = q - qi * NN;
    const int pbq = qi * (2 * WW) + qj * 2;
    const bool p3e = (pair == 3);
#pragma unroll
    for (int t = 0; t < 4; t++) {
        if (act[t]) {
            const float ay = p3e ? 0.f : acc[t].y; // s=7 garbage -> +0.0 no-op
            float* dst = out + offs[t] + pbq;      // 8B-aligned
            asm volatile("red.global.add.v2.f32 [%0], {%1, %2};"
                         :: "l"(dst), "f"(acc[t].x), "f"(ay)
                         : "memory");
        }
    }
}

// ---------------------------------------------------------------------------
extern "C" void kernel_launch(void* const* d_in, const int* in_sizes, int n_in,
                              void* d_out, int out_size) {
    const float* x    = (const float*)d_in[0];
    const float* xe   = (const float*)d_in[1];
    const float* ye   = (const float*)d_in[2];
    const int*   inds = (const int*)  d_in[3];
    float*       out  = (float*)d_out;
    (void)in_sizes; (void)n_in;

    cudaMemsetAsync(out, 0, (size_t)out_size * sizeof(float));
    agg_scatter_kernel<<<(NQ + 7) / 8, 256>>>(x, xe, ye, inds, out);
}